// round 1
// baseline (speedup 1.0000x reference)
#include <cuda_runtime.h>
#include <math.h>

// Problem constants
#define B_SZ 8
#define S_SZ 2048
#define D_SZ 1024
#define H_SZ 2048
#define M_TOT (B_SZ * S_SZ)   // 16384 rows (we compute s=0 too, overwritten later)

// Scratch for GEMM1 output: 16384 x 2048 fp32 = 128 Mi floats
__device__ float g_tmp[(size_t)M_TOT * H_SZ];

#define BM 128
#define BN 128
#define BK 8
#define TM 8
#define TN 8
#define NTHREADS 256

template<bool DO_GELU>
__global__ __launch_bounds__(NTHREADS)
void sgemm_bias_kernel(const float* __restrict__ A,   // [M, K] row-major
                       const float* __restrict__ Bm,  // [K, N] row-major
                       const float* __restrict__ bias,// [N]
                       float* __restrict__ C,         // [M, N]
                       int M, int N, int K)
{
    __shared__ float As[BK][BM];   // transposed A tile
    __shared__ float Bs[BK][BN];

    const int tid  = threadIdx.x;
    const int brow = blockIdx.y;
    const int bcol = blockIdx.x;

    const float* Ablk = A + (size_t)brow * BM * K;
    const float* Bblk = Bm + (size_t)bcol * BN;

    // 16x16 thread grid, each thread owns an 8x8 microtile
    const int tcol = tid % (BN / TN);   // 0..15
    const int trow = tid / (BN / TN);   // 0..15

    // Global->shared load mapping (float4)
    const int aRow = tid / 2;            // 0..127
    const int aCol = (tid % 2) * 4;      // 0 or 4
    const int bRow = tid / 32;           // 0..7
    const int bCol = (tid % 32) * 4;     // 0..124

    float acc[TM][TN] = {};

    for (int k0 = 0; k0 < K; k0 += BK) {
        float4 av = *(const float4*)(Ablk + (size_t)aRow * K + k0 + aCol);
        As[aCol + 0][aRow] = av.x;
        As[aCol + 1][aRow] = av.y;
        As[aCol + 2][aRow] = av.z;
        As[aCol + 3][aRow] = av.w;

        float4 bv = *(const float4*)(Bblk + (size_t)(k0 + bRow) * N + bCol);
        *(float4*)&Bs[bRow][bCol] = bv;

        __syncthreads();

        #pragma unroll
        for (int k = 0; k < BK; ++k) {
            float ar[TM], br[TN];
            #pragma unroll
            for (int i = 0; i < TM; ++i) ar[i] = As[k][trow * TM + i];
            #pragma unroll
            for (int j = 0; j < TN; ++j) br[j] = Bs[k][tcol * TN + j];
            #pragma unroll
            for (int i = 0; i < TM; ++i)
                #pragma unroll
                for (int j = 0; j < TN; ++j)
                    acc[i][j] += ar[i] * br[j];
        }
        __syncthreads();
    }

    // Epilogue: bias (+ exact GELU), vectorized fp32 stores
    const int colBase = bcol * BN + tcol * TN;
    #pragma unroll
    for (int i = 0; i < TM; ++i) {
        const int row = brow * BM + trow * TM + i;
        float* Crow = C + (size_t)row * N + colBase;
        #pragma unroll
        for (int j = 0; j < TN; j += 4) {
            float4 v;
            float t0 = acc[i][j + 0] + bias[colBase + j + 0];
            float t1 = acc[i][j + 1] + bias[colBase + j + 1];
            float t2 = acc[i][j + 2] + bias[colBase + j + 2];
            float t3 = acc[i][j + 3] + bias[colBase + j + 3];
            if (DO_GELU) {
                t0 = 0.5f * t0 * (1.0f + erff(t0 * 0.70710678118654752f));
                t1 = 0.5f * t1 * (1.0f + erff(t1 * 0.70710678118654752f));
                t2 = 0.5f * t2 * (1.0f + erff(t2 * 0.70710678118654752f));
                t3 = 0.5f * t3 * (1.0f + erff(t3 * 0.70710678118654752f));
            }
            v.x = t0; v.y = t1; v.z = t2; v.w = t3;
            *(float4*)(Crow + j) = v;
        }
    }
}

// Overwrite the 8 s==0 output rows with the corresponding input rows.
__global__ void copy_first_token_kernel(const float* __restrict__ X,
                                        float* __restrict__ out)
{
    int i = blockIdx.x * blockDim.x + threadIdx.x;   // 0 .. 8*1024-1
    if (i >= B_SZ * D_SZ) return;
    int b = i >> 10;          // / 1024
    int d = i & 1023;
    size_t off = ((size_t)b * S_SZ) * D_SZ + d;      // row s=0 of batch b
    out[off] = X[off];
}

extern "C" void kernel_launch(void* const* d_in, const int* in_sizes, int n_in,
                              void* d_out, int out_size)
{
    (void)in_sizes; (void)n_in; (void)out_size;
    const float* X  = (const float*)d_in[0];  // [8, 2048, 1024]
    const float* W1 = (const float*)d_in[1];  // [1024, 2048]
    const float* b1 = (const float*)d_in[2];  // [2048]
    const float* W2 = (const float*)d_in[3];  // [2048, 1024]
    const float* b2 = (const float*)d_in[4];  // [1024]
    float* out = (float*)d_out;               // [8, 2048, 1024]

    float* tmp = nullptr;
    cudaGetSymbolAddress((void**)&tmp, g_tmp);

    // GEMM1: tmp = GELU(X @ W1 + b1)   [16384 x 2048]
    {
        dim3 grid(H_SZ / BN, M_TOT / BM);   // (16, 128)
        sgemm_bias_kernel<true><<<grid, NTHREADS>>>(X, W1, b1, tmp,
                                                    M_TOT, H_SZ, D_SZ);
    }
    // GEMM2: out = tmp @ W2 + b2       [16384 x 1024]
    {
        dim3 grid(D_SZ / BN, M_TOT / BM);   // (8, 128)
        sgemm_bias_kernel<false><<<grid, NTHREADS>>>(tmp, W2, b2, out,
                                                     M_TOT, D_SZ, H_SZ);
    }
    // Fix up s == 0 rows: out[:,0,:] = X[:,0,:]
    copy_first_token_kernel<<<(B_SZ * D_SZ + 255) / 256, 256>>>(X, out);
}

// round 3
// speedup vs baseline: 2.8406x; 2.8406x over previous
#include <cuda_runtime.h>
#include <cuda_bf16.h>
#include <cstdint>
#include <math.h>

#define B_SZ 8
#define S_SZ 2048
#define D_SZ 1024
#define H_SZ 2048
#define M_TOT 16384

// ---------------- scratch (device globals) ------------------------------------
__device__ __nv_bfloat16 g_Xhi[(size_t)M_TOT * D_SZ];
__device__ __nv_bfloat16 g_Xlo[(size_t)M_TOT * D_SZ];
__device__ __nv_bfloat16 g_W1Thi[(size_t)H_SZ * D_SZ];   // [N=2048][K=1024]
__device__ __nv_bfloat16 g_W1Tlo[(size_t)H_SZ * D_SZ];
__device__ __nv_bfloat16 g_W2Thi[(size_t)D_SZ * H_SZ];   // [N=1024][K=2048]
__device__ __nv_bfloat16 g_W2Tlo[(size_t)D_SZ * H_SZ];
__device__ __nv_bfloat16 g_Thi[(size_t)M_TOT * H_SZ];
__device__ __nv_bfloat16 g_Tlo[(size_t)M_TOT * H_SZ];

// ---------------- small PTX helpers (all sm_80-level, compute_103-safe) -------
static __device__ __forceinline__ uint32_t smem_u32(const void* p) {
    uint32_t a;
    asm("{ .reg .u64 t; cvta.to.shared.u64 t, %1; cvt.u32.u64 %0, t; }"
        : "=r"(a) : "l"(p));
    return a;
}
static __device__ __forceinline__ void cpasync16(uint32_t dst, const void* src) {
    asm volatile("cp.async.cg.shared.global [%0], [%1], 16;"
                 :: "r"(dst), "l"(src) : "memory");
}
static __device__ __forceinline__ void cp_commit() {
    asm volatile("cp.async.commit_group;" ::: "memory");
}
template<int N>
static __device__ __forceinline__ void cp_wait() {
    asm volatile("cp.async.wait_group %0;" :: "n"(N) : "memory");
}
static __device__ __forceinline__ void ldsm4(uint32_t* r, uint32_t addr) {
    asm volatile("ldmatrix.sync.aligned.m8n8.x4.shared.b16 {%0,%1,%2,%3}, [%4];"
                 : "=r"(r[0]), "=r"(r[1]), "=r"(r[2]), "=r"(r[3]) : "r"(addr));
}
static __device__ __forceinline__ void mma16816(float* d, const uint32_t* a,
                                                uint32_t b0, uint32_t b1) {
    asm volatile(
        "mma.sync.aligned.m16n8k16.row.col.f32.bf16.bf16.f32 "
        "{%0,%1,%2,%3}, {%4,%5,%6,%7}, {%8,%9}, {%0,%1,%2,%3};"
        : "+f"(d[0]), "+f"(d[1]), "+f"(d[2]), "+f"(d[3])
        : "r"(a[0]), "r"(a[1]), "r"(a[2]), "r"(a[3]), "r"(b0), "r"(b1));
}

// ---------------- prep kernels ------------------------------------------------
static __device__ __forceinline__ void split_one(float x, __nv_bfloat16& h, __nv_bfloat16& l) {
    h = __float2bfloat16(x);
    l = __float2bfloat16(x - __bfloat162float(h));
}

__global__ void split_kernel(const float* __restrict__ X,
                             __nv_bfloat16* __restrict__ Hi,
                             __nv_bfloat16* __restrict__ Lo, int n4) {
    int stride = gridDim.x * blockDim.x;
    for (int i = blockIdx.x * blockDim.x + threadIdx.x; i < n4; i += stride) {
        float4 v = reinterpret_cast<const float4*>(X)[i];
        __nv_bfloat16 h0,h1,h2,h3,l0,l1,l2,l3;
        split_one(v.x,h0,l0); split_one(v.y,h1,l1);
        split_one(v.z,h2,l2); split_one(v.w,h3,l3);
        uint2 ph, pl;
        ph.x = ((uint32_t)__bfloat16_as_ushort(h1) << 16) | __bfloat16_as_ushort(h0);
        ph.y = ((uint32_t)__bfloat16_as_ushort(h3) << 16) | __bfloat16_as_ushort(h2);
        pl.x = ((uint32_t)__bfloat16_as_ushort(l1) << 16) | __bfloat16_as_ushort(l0);
        pl.y = ((uint32_t)__bfloat16_as_ushort(l3) << 16) | __bfloat16_as_ushort(l2);
        reinterpret_cast<uint2*>(Hi)[i] = ph;
        reinterpret_cast<uint2*>(Lo)[i] = pl;
    }
}

// W [R][C] fp32 -> WT_hi/lo [C][R] bf16
__global__ void transpose_split_kernel(const float* __restrict__ W,
                                       __nv_bfloat16* __restrict__ Thi,
                                       __nv_bfloat16* __restrict__ Tlo,
                                       int R, int C) {
    __shared__ float t[32][33];
    int c0 = blockIdx.x * 32, r0 = blockIdx.y * 32;
    int tx = threadIdx.x, ty = threadIdx.y;
    #pragma unroll
    for (int i = ty; i < 32; i += 8)
        t[i][tx] = W[(size_t)(r0 + i) * C + c0 + tx];
    __syncthreads();
    #pragma unroll
    for (int i = ty; i < 32; i += 8) {
        float x = t[tx][i];                 // = W[r0+tx][c0+i]
        __nv_bfloat16 h, l; split_one(x, h, l);
        size_t o = (size_t)(c0 + i) * R + r0 + tx;
        Thi[o] = h; Tlo[o] = l;
    }
}

__global__ void copy_first_token_kernel(const float* __restrict__ X,
                                        float* __restrict__ out) {
    int i = blockIdx.x * blockDim.x + threadIdx.x;
    if (i >= B_SZ * D_SZ) return;
    int b = i >> 10, d = i & 1023;
    size_t off = ((size_t)b * S_SZ) * D_SZ + d;
    out[off] = X[off];
}

// ---------------- HMMA (mma.sync) split-bf16 GEMM -----------------------------
// C[M,N] = act(A·B^T + bias); A [M][K] hi/lo, B [N][K] hi/lo (K-major).
// CTA tile 128x128x32, 4-stage cp.async, 8 warps of 64x32.
#define GBM 128
#define GBN 128
#define GBK 32
#define STAGES 4
#define NTHR 256
#define STG_B 32768                 // Ahi 8K | Alo 8K | Bhi 8K | Blo 8K
#define AHI_O 0
#define ALO_O 8192
#define BHI_O 16384
#define BLO_O 24576
#define SMEM_REQ (STAGES * STG_B)   // 128KB

template<int K_TOT, bool FUSE1>
__global__ __launch_bounds__(NTHR, 1)
void hmma_gemm(const __nv_bfloat16* __restrict__ Ahi,
               const __nv_bfloat16* __restrict__ Alo,
               const __nv_bfloat16* __restrict__ Bhi,
               const __nv_bfloat16* __restrict__ Blo,
               const float* __restrict__ bias,
               __nv_bfloat16* __restrict__ OutHi,
               __nv_bfloat16* __restrict__ OutLo,
               float* __restrict__ OutF,
               int Ncols)
{
    extern __shared__ char smem_raw[];
    const uint32_t sbase = smem_u32(smem_raw);

    const int tid = threadIdx.x;
    const int wid = tid >> 5;
    const int l   = tid & 31;
    const int m0  = blockIdx.y * GBM;
    const int n0  = blockIdx.x * GBN;
    const int wm  = wid & 1;        // 2 warp-rows of 64
    const int wn  = wid >> 1;       // 4 warp-cols of 32

    // ---- global->smem load plan: 8 x 16B units per thread -------------------
    // 2048 units: [0,512)=Ahi, [512,1024)=Alo, [1024,1536)=Bhi, [1536,2048)=Blo
    const char* gptr[8];
    uint32_t    soff[8];
    #pragma unroll
    for (int i = 0; i < 8; ++i) {
        int u = i * NTHR + tid;
        int mat = u >> 9;
        int w = u & 511;
        int r = w >> 2, c = w & 3;
        const __nv_bfloat16* src = (mat == 0) ? Ahi : (mat == 1) ? Alo
                                 : (mat == 2) ? Bhi : Blo;
        int grow = ((mat < 2) ? m0 : n0) + r;
        gptr[i] = (const char*)(src + (size_t)grow * K_TOT + c * 8);
        soff[i] = (uint32_t)(mat * 8192 + r * 64) + ((uint32_t)(c ^ ((r >> 1) & 3)) << 4);
    }

    // ---- ldmatrix per-lane address pieces (swizzle: chunk' = c ^ ((row>>1)&3))
    uint32_t aoff[4], axor[4];
    #pragma unroll
    for (int mi = 0; mi < 4; ++mi) {
        int row = wm * 64 + mi * 16 + ((l >> 3) & 1) * 8 + (l & 7);
        aoff[mi] = (uint32_t)row * 64;
        axor[mi] = (uint32_t)((row >> 1) & 3) << 4;
    }
    uint32_t boff[2], bxor[2];
    #pragma unroll
    for (int ni = 0; ni < 2; ++ni) {
        int row = wn * 32 + ni * 16 + ((l >> 4) & 1) * 8 + (l & 7);
        boff[ni] = (uint32_t)row * 64;
        bxor[ni] = (uint32_t)((row >> 1) & 3) << 4;
    }
    const uint32_t a_c = (uint32_t)(l >> 4);        // A k-chunk select per lane
    const uint32_t b_c = (uint32_t)((l >> 3) & 1);  // B k-chunk select per lane

    float acc[4][4][4];
    #pragma unroll
    for (int i = 0; i < 4; ++i)
        #pragma unroll
        for (int j = 0; j < 4; ++j)
            #pragma unroll
            for (int q = 0; q < 4; ++q) acc[i][j][q] = 0.f;

    constexpr int NC = K_TOT / GBK;

    // prologue: fill STAGES-1 stages
    #pragma unroll
    for (int s = 0; s < STAGES - 1; ++s) {
        uint32_t sb = sbase + (uint32_t)s * STG_B;
        #pragma unroll
        for (int i = 0; i < 8; ++i)
            cpasync16(sb + soff[i], gptr[i] + (size_t)s * 64);
        cp_commit();
    }

    #pragma unroll 1
    for (int c = 0; c < NC; ++c) {
        cp_wait<STAGES - 2>();
        __syncthreads();

        // prefetch chunk c+STAGES-1 (stage freed by iteration c-1)
        int pf = c + STAGES - 1;
        if (pf < NC) {
            uint32_t sb = sbase + (uint32_t)(pf % STAGES) * STG_B;
            #pragma unroll
            for (int i = 0; i < 8; ++i)
                cpasync16(sb + soff[i], gptr[i] + (size_t)pf * 64);
        }
        cp_commit();

        const uint32_t sb = sbase + (uint32_t)(c % STAGES) * STG_B;
        #pragma unroll
        for (int step = 0; step < 2; ++step) {
            const uint32_t acx = ((uint32_t)(step * 2) + a_c) << 4;
            const uint32_t bcx = ((uint32_t)(step * 2) + b_c) << 4;

            uint32_t Ah[4][4], Al[4][4], Bh[2][4], Bl[2][4];
            #pragma unroll
            for (int mi = 0; mi < 4; ++mi) {
                ldsm4(Ah[mi], sb + AHI_O + aoff[mi] + (acx ^ axor[mi]));
                ldsm4(Al[mi], sb + ALO_O + aoff[mi] + (acx ^ axor[mi]));
            }
            #pragma unroll
            for (int ni = 0; ni < 2; ++ni) {
                ldsm4(Bh[ni], sb + BHI_O + boff[ni] + (bcx ^ bxor[ni]));
                ldsm4(Bl[ni], sb + BLO_O + boff[ni] + (bcx ^ bxor[ni]));
            }

            #pragma unroll
            for (int mi = 0; mi < 4; ++mi) {
                #pragma unroll
                for (int nj = 0; nj < 4; ++nj) {
                    const int ni = nj >> 1, h = (nj & 1) * 2;
                    mma16816(acc[mi][nj], Ah[mi], Bh[ni][h], Bh[ni][h + 1]);
                    mma16816(acc[mi][nj], Ah[mi], Bl[ni][h], Bl[ni][h + 1]);
                    mma16816(acc[mi][nj], Al[mi], Bh[ni][h], Bh[ni][h + 1]);
                }
            }
        }
    }

    // ---- epilogue -----------------------------------------------------------
    const int r_base = m0 + wm * 64 + (l >> 2);
    const int c_base = n0 + wn * 32 + (l & 3) * 2;
    #pragma unroll
    for (int mi = 0; mi < 4; ++mi) {
        #pragma unroll
        for (int nj = 0; nj < 4; ++nj) {
            const int col = c_base + nj * 8;
            const float bb0 = __ldg(bias + col);
            const float bb1 = __ldg(bias + col + 1);
            #pragma unroll
            for (int hh = 0; hh < 2; ++hh) {
                const int row = r_base + mi * 16 + hh * 8;
                float t0 = acc[mi][nj][hh * 2 + 0] + bb0;
                float t1 = acc[mi][nj][hh * 2 + 1] + bb1;
                if (FUSE1) {
                    t0 = 0.5f * t0 * (1.0f + erff(t0 * 0.70710678118654752f));
                    t1 = 0.5f * t1 * (1.0f + erff(t1 * 0.70710678118654752f));
                    __nv_bfloat16 h0, l0, h1, l1;
                    split_one(t0, h0, l0); split_one(t1, h1, l1);
                    uint32_t ph = ((uint32_t)__bfloat16_as_ushort(h1) << 16) | __bfloat16_as_ushort(h0);
                    uint32_t pl = ((uint32_t)__bfloat16_as_ushort(l1) << 16) | __bfloat16_as_ushort(l0);
                    *reinterpret_cast<uint32_t*>(OutHi + (size_t)row * Ncols + col) = ph;
                    *reinterpret_cast<uint32_t*>(OutLo + (size_t)row * Ncols + col) = pl;
                } else {
                    float2 o; o.x = t0; o.y = t1;
                    *reinterpret_cast<float2*>(OutF + (size_t)row * Ncols + col) = o;
                }
            }
        }
    }
}

// ---------------- launcher ----------------------------------------------------
extern "C" void kernel_launch(void* const* d_in, const int* in_sizes, int n_in,
                              void* d_out, int out_size) {
    (void)in_sizes; (void)n_in; (void)out_size;
    const float* X  = (const float*)d_in[0];
    const float* W1 = (const float*)d_in[1];
    const float* b1 = (const float*)d_in[2];
    const float* W2 = (const float*)d_in[3];
    const float* b2 = (const float*)d_in[4];
    float* out = (float*)d_out;

    __nv_bfloat16 *Xhi, *Xlo, *W1Thi, *W1Tlo, *W2Thi, *W2Tlo, *Thi, *Tlo;
    cudaGetSymbolAddress((void**)&Xhi,   g_Xhi);
    cudaGetSymbolAddress((void**)&Xlo,   g_Xlo);
    cudaGetSymbolAddress((void**)&W1Thi, g_W1Thi);
    cudaGetSymbolAddress((void**)&W1Tlo, g_W1Tlo);
    cudaGetSymbolAddress((void**)&W2Thi, g_W2Thi);
    cudaGetSymbolAddress((void**)&W2Tlo, g_W2Tlo);
    cudaGetSymbolAddress((void**)&Thi,   g_Thi);
    cudaGetSymbolAddress((void**)&Tlo,   g_Tlo);

    cudaFuncSetAttribute(hmma_gemm<D_SZ, true>,
                         cudaFuncAttributeMaxDynamicSharedMemorySize, SMEM_REQ);
    cudaFuncSetAttribute(hmma_gemm<H_SZ, false>,
                         cudaFuncAttributeMaxDynamicSharedMemorySize, SMEM_REQ);

    // 1) split X into hi/lo bf16
    split_kernel<<<4096, 256>>>(X, Xhi, Xlo, M_TOT * D_SZ / 4);
    // 2) transpose+split weights into K-major bf16
    transpose_split_kernel<<<dim3(H_SZ / 32, D_SZ / 32), dim3(32, 8)>>>(W1, W1Thi, W1Tlo, D_SZ, H_SZ);
    transpose_split_kernel<<<dim3(D_SZ / 32, H_SZ / 32), dim3(32, 8)>>>(W2, W2Thi, W2Tlo, H_SZ, D_SZ);
    // 3) GEMM1: T = GELU(X @ W1 + b1), split-bf16 output
    hmma_gemm<D_SZ, true><<<dim3(H_SZ / GBN, M_TOT / GBM), NTHR, SMEM_REQ>>>(
        Xhi, Xlo, W1Thi, W1Tlo, b1, Thi, Tlo, nullptr, H_SZ);
    // 4) GEMM2: out = T @ W2 + b2, fp32 output
    hmma_gemm<H_SZ, false><<<dim3(D_SZ / GBN, M_TOT / GBM), NTHR, SMEM_REQ>>>(
        Thi, Tlo, W2Thi, W2Tlo, b2, nullptr, nullptr, out, D_SZ);
    // 5) out[:,0,:] = X[:,0,:]
    copy_first_token_kernel<<<(B_SZ * D_SZ + 255) / 256, 256>>>(X, out);
}